// round 11
// baseline (speedup 1.0000x reference)
#include <cuda_runtime.h>

// ---------------------------------------------------------------------------
// QuadraticConv2DTranspose via bed-of-nails sparsity.
//   B=8,H=W=32,CIN=COUT=64,k=3,s=2 -> out [8,64,64,64]
// Parity classes (ho%2,wo%2): NT {1,2,2,4} taps -> F {2,5,5,14} features.
// R11: fully-async staging (taps via cp.async in RAW 4-cin x (row,col)
//      layout, zero-fill OOB), ONE barrier per chunk (wait_group 0 -> bar ->
//      stage-next -> compute). 16px x 4co threads, frags in regs, sliding
//      tap window. (128,3), CH=4, cin-half split, gmem partial reduction.
// ---------------------------------------------------------------------------

typedef unsigned long long u64;

__device__ float g_Kc[106496];
__device__ float g_bias[64];

// Horner-ordered feature lists: per tap a: quads (a,b) b=a..NT-1, then lin_a.
__constant__ int c_L[4][14] = {
    {30,49, 0,0,0,0,0,0,0,0,0,0,0,0},
    {24,26,48,35,50, 0,0,0,0,0,0,0,0,0},
    { 9,15,46,42,52, 0,0,0,0,0,0,0,0,0},
    { 0, 2, 6, 8,45,17,21,23,47,39,41,51,44,53}
};
__constant__ int c_off[4] = {0, 8192, 28672, 49152};
__constant__ int c_Fn[4] = {2, 5, 5, 14};

// --------------------------- preprocessing ---------------------------------

__global__ void qct_prep(const float* __restrict__ fk) {
    int idx = blockIdx.x * 256 + threadIdx.x;
    if (blockIdx.x == 0 && threadIdx.x < 64) {
        int o = threadIdx.x;
        float s = 0.f;
#pragma unroll 8
        for (int c = 0; c < 64; c++) s += fk[(54 * 64 + c) * 64 + o];
        g_bias[o] = s;
    }
    if (idx >= 4 * 14 * 4096) return;
    int C = idx / (14 * 4096);
    int r = idx % (14 * 4096);
    int f = r / 4096;
    int co = r % 4096;
    int c = co >> 6, o = co & 63;
    if (f >= c_Fn[C]) return;
    g_Kc[c_off[C] + (c * c_Fn[C] + f) * 64 + o] = fk[(c_L[C][f] * 64 + c) * 64 + o];
}

// --------------------------- helpers ---------------------------------------

__device__ __forceinline__ void fma2(u64& d, u64 a, u64 b) {
    asm("fma.rn.f32x2 %0, %1, %2, %0;" : "+l"(d) : "l"(a), "l"(b));
}
__device__ __forceinline__ u64 pack2f(float v) {
    u64 r;
    unsigned int u = __float_as_uint(v);
    asm("mov.b64 %0, {%1, %1};" : "=l"(r) : "r"(u));
    return r;
}
__device__ __forceinline__ void unpack2(u64 v, float& lo, float& hi) {
    unsigned int a, b;
    asm("mov.b64 {%0, %1}, %2;" : "=r"(a), "=r"(b) : "l"(v));
    lo = __uint_as_float(a);
    hi = __uint_as_float(b);
}
__device__ __forceinline__ void cp16(void* dst_smem, const void* src) {
    unsigned sdst = (unsigned)__cvta_generic_to_shared(dst_smem);
    asm volatile("cp.async.cg.shared.global [%0], [%1], 16;" :: "r"(sdst), "l"(src));
}
// zero-fill variant: src-size 0 -> all 16 bytes zero-filled
__device__ __forceinline__ void cp16z(void* dst_smem, const void* src, bool valid) {
    unsigned sdst = (unsigned)__cvta_generic_to_shared(dst_smem);
    int ssz = valid ? 16 : 0;
    asm volatile("cp.async.cg.shared.global [%0], [%1], 16, %2;"
                 :: "r"(sdst), "l"(src), "r"(ssz));
}
#define CP_COMMIT() asm volatile("cp.async.commit_group;")
__device__ __forceinline__ void cp_wait0() {
    asm volatile("cp.async.wait_group 0;");
}

// --------------------------- class configs ---------------------------------
// Tap a at patch offset (DR(a), DC(a)); window spans WR rows x WC cols.
// Horner layout: FS(a)=group start; quad (a,b) at FS(a)+(b-a); lin at
// FS(a)+(NT-a).

template <int C> struct Cfg;
template <> struct Cfg<0> {   // (even, even): tap j=4
    static constexpr int PY = 0, PX = 0, F = 2, OFF = 0, NT = 1, WR = 1, WC = 1;
    __host__ __device__ static constexpr int DR(int) { return 0; }
    __host__ __device__ static constexpr int DC(int) { return 0; }
    __host__ __device__ static constexpr int FS(int a) {
        int s = 0; for (int i = 0; i < a; i++) s += NT - i + 1; return s;
    }
};
template <> struct Cfg<1> {   // (even, odd): taps j=3,5
    static constexpr int PY = 0, PX = 1, F = 5, OFF = 8192, NT = 2, WR = 1, WC = 2;
    __host__ __device__ static constexpr int DR(int) { return 0; }
    __host__ __device__ static constexpr int DC(int a) { return a; }
    __host__ __device__ static constexpr int FS(int a) {
        int s = 0; for (int i = 0; i < a; i++) s += NT - i + 1; return s;
    }
};
template <> struct Cfg<2> {   // (odd, even): taps j=1,7
    static constexpr int PY = 1, PX = 0, F = 5, OFF = 28672, NT = 2, WR = 2, WC = 1;
    __host__ __device__ static constexpr int DR(int a) { return a; }
    __host__ __device__ static constexpr int DC(int) { return 0; }
    __host__ __device__ static constexpr int FS(int a) {
        int s = 0; for (int i = 0; i < a; i++) s += NT - i + 1; return s;
    }
};
template <> struct Cfg<3> {   // (odd, odd): taps j=0,2,6,8
    static constexpr int PY = 1, PX = 1, F = 14, OFF = 49152, NT = 4, WR = 2, WC = 2;
    __host__ __device__ static constexpr int DR(int a) { return a >> 1; }
    __host__ __device__ static constexpr int DC(int a) { return a & 1; }
    __host__ __device__ static constexpr int FS(int a) {
        int s = 0; for (int i = 0; i < a; i++) s += NT - i + 1; return s;
    }
};

#define CH 4

// --------------------------- staging (all cp.async) --------------------------
// Kernel frags: F*64 float4, contiguous. Taps: RAW layout — 16B per (rr,cc) =
// 4 consecutive cins (x is NHWC, cin fastest): sXr[(rr*33+cc)*4 + cl].

template <int C>
__device__ __forceinline__ void stage(const float* __restrict__ x, float* sK,
                                      float* sXr, const float* gK, int cc0,
                                      int b, int ipair, int th) {
    using Cf = Cfg<C>;
    const float4* src = (const float4*)(gK + cc0 * Cf::F * 64);
    float4* dst = (float4*)sK;
#pragma unroll
    for (int k = 0; k < Cf::F; k++)
        cp16(dst + k * 64 + th, src + k * 64 + th);
#pragma unroll
    for (int it = 0; it < 2; it++) {
        int idx = th + it * 64;
        if (idx < 99) {
            int rr = idx / 33, cc = idx % 33;
            int r = ipair * 2 + rr;
            bool valid = (r < 32) && (cc < 32);
            const float* s = valid ? (x + (((b * 32 + r) * 32 + cc) << 6) + cc0) : x;
            cp16z(sXr + idx * 4, s, valid);
        }
    }
}

// --------------------------- compute ----------------------------------------
// Per cl: all F frags (4 couts each) live in registers; 16-pixel sweep with
// sliding tap window. Horner:
//   contribution = sum_a t_a * ( K_lin_a + sum_{b>=a} t_b * K_ab ).

template <int C>
__device__ __forceinline__ void compute_chunk(const float* sK, const float* sXr,
                                              int ii, int j0, int tx,
                                              u64 acc[16][2]) {
    using Cf = Cfg<C>;
#pragma unroll
    for (int cl = 0; cl < CH; cl++) {
        const float* kb = sK + cl * Cf::F * 64 + 4 * tx;
        ulonglong2 frg[Cf::F];
#pragma unroll
        for (int f = 0; f < Cf::F; f++)
            frg[f] = *(const ulonglong2*)(kb + f * 64);

        const float* tb = sXr + cl;   // element (r,col) at ((r)*33+col)*4

        u64 win[Cf::WR][Cf::WC];
#pragma unroll
        for (int r = 0; r < Cf::WR; r++)
#pragma unroll
            for (int c = 0; c < Cf::WC; c++)
                win[r][c] = pack2f(tb[((ii + r) * 33 + j0 + c) * 4]);

#pragma unroll
        for (int p = 0; p < 16; p++) {
#pragma unroll
            for (int a = 0; a < Cf::NT; a++) {
                const int fs = Cf::FS(a);
                const int nb = Cf::NT - a;
                u64 t0 = frg[fs + nb].x;
                u64 t1 = frg[fs + nb].y;
#pragma unroll
                for (int b = Cf::NT - 1; b >= a; b--) {
                    u64 tv = win[Cf::DR(b)][Cf::DC(b)];
                    fma2(t0, tv, frg[fs + b - a].x);
                    fma2(t1, tv, frg[fs + b - a].y);
                }
                u64 ta = win[Cf::DR(a)][Cf::DC(a)];
                fma2(acc[p][0], ta, t0);
                fma2(acc[p][1], ta, t1);
            }
            if (p < 15) {
#pragma unroll
                for (int r = 0; r < Cf::WR; r++) {
#pragma unroll
                    for (int c = 0; c < Cf::WC - 1; c++) win[r][c] = win[r][c + 1];
                    win[r][Cf::WC - 1] =
                        pack2f(tb[((ii + r) * 33 + j0 + p + Cf::WC) * 4]);
                }
            }
        }
    }
}

// --------------------------- main kernel ------------------------------------
// CTA: 128 threads = two 64-thread cin-halves (h = t>>6). Per half:
// tx = th&15 -> couts 4tx..+3 ; tyy = th>>4 -> 16 pixels at m0 = 16*tyy.
// 8 chunks of 4 cins, double-buffered, ONE named barrier per chunk:
//   wait_group 0 ; bar ; stage(next) ; commit ; compute(cur)
// (wait+bar proves ALL warps' groups for cur landed; bar also proves the
//  next-buffer's previous readers finished before we overwrite it.)

template <int C>
__device__ __forceinline__ void run_tile(const float* __restrict__ x,
                                         float* __restrict__ out, int tile) {
    using Cf = Cfg<C>;
    constexpr int KSZ = CH * Cf::F * 64;      // kernel chunk floats
    constexpr int TSZ = 99 * 4;               // raw tap floats
    constexpr int BUF = KSZ + TSZ;

    extern __shared__ float sm[];

    const int t = threadIdx.x;
    const int h = t >> 6;
    const int th = t & 63;
    float* base = sm + h * 2 * BUF;

    const int b = tile >> 4;
    const int ipair = tile & 15;
    const int tx = th & 15;
    const int tyy = th >> 4;                // 0..3
    const int m0 = 16 * tyy;                // first of 16 pixels
    const int ii = m0 >> 5;                 // input row within pair
    const int j0 = m0 & 31;                 // 0 or 16

    u64 acc[16][2];
#pragma unroll
    for (int p = 0; p < 16; p++) { acc[p][0] = 0ull; acc[p][1] = 0ull; }

    const float* gK = g_Kc + Cf::OFF;
    const int cbase = h * 32;

    stage<C>(x, base, base + KSZ, gK, cbase, b, ipair, th);
    CP_COMMIT();

    for (int ch = 0; ch < 8; ch++) {
        float* cbuf = base + (ch & 1) * BUF;
        float* nbuf = base + ((ch & 1) ^ 1) * BUF;
        cp_wait0();
        asm volatile("bar.sync %0, 64;" :: "r"(1 + h));
        if (ch < 7) {
            stage<C>(x, nbuf, nbuf + KSZ, gK, cbase + (ch + 1) * CH, b, ipair, th);
            CP_COMMIT();
        }
        compute_chunk<C>(cbuf, cbuf + KSZ, ii, j0, tx, acc);
    }

    // ---- reduction epilogue ----
    const int i = ipair * 2 + ii;
    const int ho = 2 * i + Cf::PY;

    if (h == 1) {   // store partials (cin 32..63)
#pragma unroll
        for (int p = 0; p < 16; p++) {
            const int wo = 2 * (j0 + p) + Cf::PX;
            float v0, v1, v2, v3;
            unpack2(acc[p][0], v0, v1);
            unpack2(acc[p][1], v2, v3);
            float* op = out + (((b * 64 + ho) * 64 + wo) << 6) + 4 * tx;
            *(float4*)op = make_float4(v0, v1, v2, v3);
        }
    }
    __syncthreads();
    if (h == 0) {   // add partial + bias, final store
        float4 bo = *(const float4*)(g_bias + 4 * tx);
#pragma unroll
        for (int p = 0; p < 16; p++) {
            const int wo = 2 * (j0 + p) + Cf::PX;
            float* op = out + (((b * 64 + ho) * 64 + wo) << 6) + 4 * tx;
            float4 o0 = *(const float4*)op;
            float v0, v1, v2, v3;
            unpack2(acc[p][0], v0, v1);
            unpack2(acc[p][1], v2, v3);
            *(float4*)op = make_float4(v0 + bo.x + o0.x, v1 + bo.y + o0.y,
                                       v2 + bo.z + o0.z, v3 + bo.w + o0.w);
        }
    }
}

__global__ __launch_bounds__(128, 3) void qct_main(const float* __restrict__ x,
                                                   float* __restrict__ out) {
    int id = blockIdx.x;
    // heavy class 3 first for wave balance
    if (id < 128)      run_tile<3>(x, out, id);
    else if (id < 256) run_tile<1>(x, out, id - 128);
    else if (id < 384) run_tile<2>(x, out, id - 256);
    else               run_tile<0>(x, out, id - 384);
}

// --------------------------- launch ----------------------------------------

extern "C" void kernel_launch(void* const* d_in, const int* in_sizes, int n_in,
                              void* d_out, int out_size) {
    const float* x  = (const float*)d_in[0];
    const float* fk = (const float*)d_in[1];
    if (n_in >= 2 && in_sizes[0] == 55 * 64 * 64) {  // defensive order check
        const float* tmp = x; x = fk; fk = tmp;
    }
    float* out = (float*)d_out;

    qct_prep<<<(4 * 14 * 4096 + 255) / 256, 256>>>(fk);

    // 2 halves x 2 buffers of (kernel chunk + raw taps), sized for class 3
    const int smem_bytes = 4 * (CH * 14 * 64 + 99 * 4) * 4;  // 63680
    cudaFuncSetAttribute(qct_main, cudaFuncAttributeMaxDynamicSharedMemorySize,
                         smem_bytes);
    qct_main<<<512, 128, smem_bytes>>>(x, out);
}

// round 12
// speedup vs baseline: 1.2379x; 1.2379x over previous
#include <cuda_runtime.h>

// ---------------------------------------------------------------------------
// QuadraticConv2DTranspose via bed-of-nails sparsity.
//   B=8,H=W=32,CIN=COUT=64,k=3,s=2 -> out [8,64,64,64]
// Parity classes (ho%2,wo%2): NT {1,2,2,4} taps -> F {2,5,5,14} features.
// R12: R10 base (best: coalesced LDG->STS tap staging, 16px x 4co threads,
//      frags in regs, sliding tap window) + single barrier per chunk
//      (wait_group 0 -> bar -> stage-next -> compute). R11's tiny-cp.async
//      tap staging reverted (caused L2/alu blowup).
//      (128,3), CH=4, two 64-thr cin-halves, gmem partial reduction.
// ---------------------------------------------------------------------------

typedef unsigned long long u64;

__device__ float g_Kc[106496];
__device__ float g_bias[64];

// Horner-ordered feature lists: per tap a: quads (a,b) b=a..NT-1, then lin_a.
__constant__ int c_L[4][14] = {
    {30,49, 0,0,0,0,0,0,0,0,0,0,0,0},
    {24,26,48,35,50, 0,0,0,0,0,0,0,0,0},
    { 9,15,46,42,52, 0,0,0,0,0,0,0,0,0},
    { 0, 2, 6, 8,45,17,21,23,47,39,41,51,44,53}
};
__constant__ int c_off[4] = {0, 8192, 28672, 49152};
__constant__ int c_Fn[4] = {2, 5, 5, 14};

// --------------------------- preprocessing ---------------------------------

__global__ void qct_prep(const float* __restrict__ fk) {
    int idx = blockIdx.x * 256 + threadIdx.x;
    if (blockIdx.x == 0 && threadIdx.x < 64) {
        int o = threadIdx.x;
        float s = 0.f;
#pragma unroll 8
        for (int c = 0; c < 64; c++) s += fk[(54 * 64 + c) * 64 + o];
        g_bias[o] = s;
    }
    if (idx >= 4 * 14 * 4096) return;
    int C = idx / (14 * 4096);
    int r = idx % (14 * 4096);
    int f = r / 4096;
    int co = r % 4096;
    int c = co >> 6, o = co & 63;
    if (f >= c_Fn[C]) return;
    g_Kc[c_off[C] + (c * c_Fn[C] + f) * 64 + o] = fk[(c_L[C][f] * 64 + c) * 64 + o];
}

// --------------------------- helpers ---------------------------------------

__device__ __forceinline__ void fma2(u64& d, u64 a, u64 b) {
    asm("fma.rn.f32x2 %0, %1, %2, %0;" : "+l"(d) : "l"(a), "l"(b));
}
__device__ __forceinline__ u64 pack2f(float v) {
    u64 r;
    unsigned int u = __float_as_uint(v);
    asm("mov.b64 %0, {%1, %1};" : "=l"(r) : "r"(u));
    return r;
}
__device__ __forceinline__ void unpack2(u64 v, float& lo, float& hi) {
    unsigned int a, b;
    asm("mov.b64 {%0, %1}, %2;" : "=r"(a), "=r"(b) : "l"(v));
    lo = __uint_as_float(a);
    hi = __uint_as_float(b);
}
__device__ __forceinline__ void cp16(void* dst_smem, const void* src) {
    unsigned sdst = (unsigned)__cvta_generic_to_shared(dst_smem);
    asm volatile("cp.async.cg.shared.global [%0], [%1], 16;" :: "r"(sdst), "l"(src));
}
#define CP_COMMIT() asm volatile("cp.async.commit_group;")
__device__ __forceinline__ void cp_wait0() {
    asm volatile("cp.async.wait_group 0;");
}

// --------------------------- class configs ---------------------------------
// Tap a at patch offset (DR(a), DC(a)); window spans WR rows x WC cols.
// Horner layout: FS(a)=group start; quad (a,b) at FS(a)+(b-a); lin at
// FS(a)+(NT-a).

template <int C> struct Cfg;
template <> struct Cfg<0> {   // (even, even): tap j=4
    static constexpr int PY = 0, PX = 0, F = 2, OFF = 0, NT = 1, WR = 1, WC = 1;
    __host__ __device__ static constexpr int DR(int) { return 0; }
    __host__ __device__ static constexpr int DC(int) { return 0; }
    __host__ __device__ static constexpr int FS(int a) {
        int s = 0; for (int i = 0; i < a; i++) s += NT - i + 1; return s;
    }
};
template <> struct Cfg<1> {   // (even, odd): taps j=3,5
    static constexpr int PY = 0, PX = 1, F = 5, OFF = 8192, NT = 2, WR = 1, WC = 2;
    __host__ __device__ static constexpr int DR(int) { return 0; }
    __host__ __device__ static constexpr int DC(int a) { return a; }
    __host__ __device__ static constexpr int FS(int a) {
        int s = 0; for (int i = 0; i < a; i++) s += NT - i + 1; return s;
    }
};
template <> struct Cfg<2> {   // (odd, even): taps j=1,7
    static constexpr int PY = 1, PX = 0, F = 5, OFF = 28672, NT = 2, WR = 2, WC = 1;
    __host__ __device__ static constexpr int DR(int a) { return a; }
    __host__ __device__ static constexpr int DC(int) { return 0; }
    __host__ __device__ static constexpr int FS(int a) {
        int s = 0; for (int i = 0; i < a; i++) s += NT - i + 1; return s;
    }
};
template <> struct Cfg<3> {   // (odd, odd): taps j=0,2,6,8
    static constexpr int PY = 1, PX = 1, F = 14, OFF = 49152, NT = 4, WR = 2, WC = 2;
    __host__ __device__ static constexpr int DR(int a) { return a >> 1; }
    __host__ __device__ static constexpr int DC(int a) { return a & 1; }
    __host__ __device__ static constexpr int FS(int a) {
        int s = 0; for (int i = 0; i < a; i++) s += NT - i + 1; return s;
    }
};

#define CH 4

// --------------------------- staging ----------------------------------------
// Chunk = 4 cins. Kernel frags (4*F*64 floats) via cp.async; taps via
// coalesced float4 LDG -> 4x STS, PLAIN f32 layout sXu[cl][3 rows][34 cols].

template <int C>
__device__ __forceinline__ void stage(const float* __restrict__ x, float* sK,
                                      float* sXu, const float* gK, int cc0,
                                      int b, int ipair, int th) {
    using Cf = Cfg<C>;
    const float4* src = (const float4*)(gK + cc0 * Cf::F * 64);
    float4* dst = (float4*)sK;
#pragma unroll
    for (int k = 0; k < Cf::F; k++)
        cp16(dst + k * 64 + th, src + k * 64 + th);
#pragma unroll
    for (int it = 0; it < 2; it++) {
        int idx = th + it * 64;
        if (idx < 99) {
            int rr = idx / 33, cc = idx % 33;
            int r = ipair * 2 + rr;
            float4 v = make_float4(0.f, 0.f, 0.f, 0.f);
            if (r < 32 && cc < 32)
                v = *(const float4*)(x + (((b * 32 + r) * 32 + cc) << 6) + cc0);
            sXu[(0 * 3 + rr) * 34 + cc] = v.x;
            sXu[(1 * 3 + rr) * 34 + cc] = v.y;
            sXu[(2 * 3 + rr) * 34 + cc] = v.z;
            sXu[(3 * 3 + rr) * 34 + cc] = v.w;
        }
    }
}

// --------------------------- compute ----------------------------------------
// Per cl: all F frags (4 couts each) live in registers; 16-pixel sweep with
// sliding tap window. Horner:
//   contribution = sum_a t_a * ( K_lin_a + sum_{b>=a} t_b * K_ab ).

template <int C>
__device__ __forceinline__ void compute_chunk(const float* sK, const float* sXu,
                                              int ii, int j0, int tx,
                                              u64 acc[16][2]) {
    using Cf = Cfg<C>;
#pragma unroll
    for (int cl = 0; cl < CH; cl++) {
        const float* kb = sK + cl * Cf::F * 64 + 4 * tx;
        ulonglong2 frg[Cf::F];
#pragma unroll
        for (int f = 0; f < Cf::F; f++)
            frg[f] = *(const ulonglong2*)(kb + f * 64);

        const float* tb = sXu + (cl * 3 + ii) * 34 + j0;

        u64 win[Cf::WR][Cf::WC];
#pragma unroll
        for (int r = 0; r < Cf::WR; r++)
#pragma unroll
            for (int c = 0; c < Cf::WC; c++)
                win[r][c] = pack2f(tb[r * 34 + c]);

#pragma unroll
        for (int p = 0; p < 16; p++) {
#pragma unroll
            for (int a = 0; a < Cf::NT; a++) {
                const int fs = Cf::FS(a);
                const int nb = Cf::NT - a;
                u64 t0 = frg[fs + nb].x;
                u64 t1 = frg[fs + nb].y;
#pragma unroll
                for (int b = Cf::NT - 1; b >= a; b--) {
                    u64 tv = win[Cf::DR(b)][Cf::DC(b)];
                    fma2(t0, tv, frg[fs + b - a].x);
                    fma2(t1, tv, frg[fs + b - a].y);
                }
                u64 ta = win[Cf::DR(a)][Cf::DC(a)];
                fma2(acc[p][0], ta, t0);
                fma2(acc[p][1], ta, t1);
            }
            if (p < 15) {
#pragma unroll
                for (int r = 0; r < Cf::WR; r++) {
#pragma unroll
                    for (int c = 0; c < Cf::WC - 1; c++) win[r][c] = win[r][c + 1];
                    win[r][Cf::WC - 1] = pack2f(tb[r * 34 + p + Cf::WC]);
                }
            }
        }
    }
}

// --------------------------- main kernel ------------------------------------
// CTA: 128 threads = two 64-thread cin-halves (h = t>>6). Per half:
// tx = th&15 -> couts 4tx..+3 ; tyy = th>>4 -> 16 pixels at m0 = 16*tyy.
// 8 chunks of 4 cins, double-buffered, ONE named barrier per chunk:
//   wait_group 0 ; bar ; stage(next) ; commit ; compute(cur)
// The bar proves (a) every warp's cp groups for cur landed and its tap STS
// are visible, (b) every warp finished reading next-buffer last iteration.

template <int C>
__device__ __forceinline__ void run_tile(const float* __restrict__ x,
                                         float* __restrict__ out, int tile) {
    using Cf = Cfg<C>;
    constexpr int KSZ = CH * Cf::F * 64;      // kernel chunk floats
    constexpr int TSZ = CH * 3 * 34;          // plain tap floats
    constexpr int BUF = KSZ + TSZ;

    extern __shared__ float sm[];

    const int t = threadIdx.x;
    const int h = t >> 6;
    const int th = t & 63;
    float* base = sm + h * 2 * BUF;

    const int b = tile >> 4;
    const int ipair = tile & 15;
    const int tx = th & 15;
    const int tyy = th >> 4;                // 0..3
    const int m0 = 16 * tyy;                // first of 16 pixels
    const int ii = m0 >> 5;                 // input row within pair
    const int j0 = m0 & 31;                 // 0 or 16

    u64 acc[16][2];
#pragma unroll
    for (int p = 0; p < 16; p++) { acc[p][0] = 0ull; acc[p][1] = 0ull; }

    const float* gK = g_Kc + Cf::OFF;
    const int cbase = h * 32;

    stage<C>(x, base, base + KSZ, gK, cbase, b, ipair, th);
    CP_COMMIT();

    for (int ch = 0; ch < 8; ch++) {
        float* cbuf = base + (ch & 1) * BUF;
        float* nbuf = base + ((ch & 1) ^ 1) * BUF;
        cp_wait0();
        asm volatile("bar.sync %0, 64;" :: "r"(1 + h));
        if (ch < 7) {
            stage<C>(x, nbuf, nbuf + KSZ, gK, cbase + (ch + 1) * CH, b, ipair, th);
            CP_COMMIT();
        }
        compute_chunk<C>(cbuf, cbuf + KSZ, ii, j0, tx, acc);
    }

    // ---- reduction epilogue ----
    const int i = ipair * 2 + ii;
    const int ho = 2 * i + Cf::PY;

    if (h == 1) {   // store partials (cin 32..63)
#pragma unroll
        for (int p = 0; p < 16; p++) {
            const int wo = 2 * (j0 + p) + Cf::PX;
            float v0, v1, v2, v3;
            unpack2(acc[p][0], v0, v1);
            unpack2(acc[p][1], v2, v3);
            float* op = out + (((b * 64 + ho) * 64 + wo) << 6) + 4 * tx;
            *(float4*)op = make_float4(v0, v1, v2, v3);
        }
    }
    __syncthreads();
    if (h == 0) {   // add partial + bias, final store
        float4 bo = *(const float4*)(g_bias + 4 * tx);
#pragma unroll
        for (int p = 0; p < 16; p++) {
            const int wo = 2 * (j0 + p) + Cf::PX;
            float* op = out + (((b * 64 + ho) * 64 + wo) << 6) + 4 * tx;
            float4 o0 = *(const float4*)op;
            float v0, v1, v2, v3;
            unpack2(acc[p][0], v0, v1);
            unpack2(acc[p][1], v2, v3);
            *(float4*)op = make_float4(v0 + bo.x + o0.x, v1 + bo.y + o0.y,
                                       v2 + bo.z + o0.z, v3 + bo.w + o0.w);
        }
    }
}

__global__ __launch_bounds__(128, 3) void qct_main(const float* __restrict__ x,
                                                   float* __restrict__ out) {
    int id = blockIdx.x;
    // heavy class 3 first for wave balance
    if (id < 128)      run_tile<3>(x, out, id);
    else if (id < 256) run_tile<1>(x, out, id - 128);
    else if (id < 384) run_tile<2>(x, out, id - 256);
    else               run_tile<0>(x, out, id - 384);
}

// --------------------------- launch ----------------------------------------

extern "C" void kernel_launch(void* const* d_in, const int* in_sizes, int n_in,
                              void* d_out, int out_size) {
    const float* x  = (const float*)d_in[0];
    const float* fk = (const float*)d_in[1];
    if (n_in >= 2 && in_sizes[0] == 55 * 64 * 64) {  // defensive order check
        const float* tmp = x; x = fk; fk = tmp;
    }
    float* out = (float*)d_out;

    qct_prep<<<(4 * 14 * 4096 + 255) / 256, 256>>>(fk);

    // 2 halves x 2 buffers of (kernel chunk + plain taps), sized for class 3
    const int smem_bytes = 4 * (CH * 14 * 64 + CH * 3 * 34) * 4;  // 63872
    cudaFuncSetAttribute(qct_main, cudaFuncAttributeMaxDynamicSharedMemorySize,
                         smem_bytes);
    qct_main<<<512, 128, smem_bytes>>>(x, out);
}

// round 13
// speedup vs baseline: 1.2549x; 1.0137x over previous
#include <cuda_runtime.h>

// ---------------------------------------------------------------------------
// QuadraticConv2DTranspose via bed-of-nails sparsity.
//   B=8,H=W=32,CIN=COUT=64,k=3,s=2 -> out [8,64,64,64]
// Parity classes (ho%2,wo%2): NT {1,2,2,4} taps -> F {2,5,5,14} features.
// R13: halve per-thread state (16px x 2co, 32 acc regs, ~90 regs total) and
//      double threads/CTA to 256 -> (256,2) = 16 warps/SM (+33% latency
//      cover vs the reg-capped 12). Same proven pieces: frags in regs,
//      sliding tap window, coalesced LDG->STS taps + cp.async kernel frags,
//      one barrier per chunk, CH=4, cin-half split, gmem partial reduction.
// ---------------------------------------------------------------------------

typedef unsigned long long u64;

__device__ float g_Kc[106496];
__device__ float g_bias[64];

// Horner-ordered feature lists: per tap a: quads (a,b) b=a..NT-1, then lin_a.
__constant__ int c_L[4][14] = {
    {30,49, 0,0,0,0,0,0,0,0,0,0,0,0},
    {24,26,48,35,50, 0,0,0,0,0,0,0,0,0},
    { 9,15,46,42,52, 0,0,0,0,0,0,0,0,0},
    { 0, 2, 6, 8,45,17,21,23,47,39,41,51,44,53}
};
__constant__ int c_off[4] = {0, 8192, 28672, 49152};
__constant__ int c_Fn[4] = {2, 5, 5, 14};

// --------------------------- preprocessing ---------------------------------

__global__ void qct_prep(const float* __restrict__ fk) {
    int idx = blockIdx.x * 256 + threadIdx.x;
    if (blockIdx.x == 0 && threadIdx.x < 64) {
        int o = threadIdx.x;
        float s = 0.f;
#pragma unroll 8
        for (int c = 0; c < 64; c++) s += fk[(54 * 64 + c) * 64 + o];
        g_bias[o] = s;
    }
    if (idx >= 4 * 14 * 4096) return;
    int C = idx / (14 * 4096);
    int r = idx % (14 * 4096);
    int f = r / 4096;
    int co = r % 4096;
    int c = co >> 6, o = co & 63;
    if (f >= c_Fn[C]) return;
    g_Kc[c_off[C] + (c * c_Fn[C] + f) * 64 + o] = fk[(c_L[C][f] * 64 + c) * 64 + o];
}

// --------------------------- helpers ---------------------------------------

__device__ __forceinline__ void fma2(u64& d, u64 a, u64 b) {
    asm("fma.rn.f32x2 %0, %1, %2, %0;" : "+l"(d) : "l"(a), "l"(b));
}
__device__ __forceinline__ u64 pack2f(float v) {
    u64 r;
    unsigned int u = __float_as_uint(v);
    asm("mov.b64 %0, {%1, %1};" : "=l"(r) : "r"(u));
    return r;
}
__device__ __forceinline__ void unpack2(u64 v, float& lo, float& hi) {
    unsigned int a, b;
    asm("mov.b64 {%0, %1}, %2;" : "=r"(a), "=r"(b) : "l"(v));
    lo = __uint_as_float(a);
    hi = __uint_as_float(b);
}
__device__ __forceinline__ void cp16(void* dst_smem, const void* src) {
    unsigned sdst = (unsigned)__cvta_generic_to_shared(dst_smem);
    asm volatile("cp.async.cg.shared.global [%0], [%1], 16;" :: "r"(sdst), "l"(src));
}
#define CP_COMMIT() asm volatile("cp.async.commit_group;")
__device__ __forceinline__ void cp_wait0() {
    asm volatile("cp.async.wait_group 0;");
}

// --------------------------- class configs ---------------------------------
// Tap a at patch offset (DR(a), DC(a)); window spans WR rows x WC cols.
// Horner layout: FS(a)=group start; quad (a,b) at FS(a)+(b-a); lin at
// FS(a)+(NT-a).

template <int C> struct Cfg;
template <> struct Cfg<0> {   // (even, even): tap j=4
    static constexpr int PY = 0, PX = 0, F = 2, OFF = 0, NT = 1, WR = 1, WC = 1;
    __host__ __device__ static constexpr int DR(int) { return 0; }
    __host__ __device__ static constexpr int DC(int) { return 0; }
    __host__ __device__ static constexpr int FS(int a) {
        int s = 0; for (int i = 0; i < a; i++) s += NT - i + 1; return s;
    }
};
template <> struct Cfg<1> {   // (even, odd): taps j=3,5
    static constexpr int PY = 0, PX = 1, F = 5, OFF = 8192, NT = 2, WR = 1, WC = 2;
    __host__ __device__ static constexpr int DR(int) { return 0; }
    __host__ __device__ static constexpr int DC(int a) { return a; }
    __host__ __device__ static constexpr int FS(int a) {
        int s = 0; for (int i = 0; i < a; i++) s += NT - i + 1; return s;
    }
};
template <> struct Cfg<2> {   // (odd, even): taps j=1,7
    static constexpr int PY = 1, PX = 0, F = 5, OFF = 28672, NT = 2, WR = 2, WC = 1;
    __host__ __device__ static constexpr int DR(int a) { return a; }
    __host__ __device__ static constexpr int DC(int) { return 0; }
    __host__ __device__ static constexpr int FS(int a) {
        int s = 0; for (int i = 0; i < a; i++) s += NT - i + 1; return s;
    }
};
template <> struct Cfg<3> {   // (odd, odd): taps j=0,2,6,8
    static constexpr int PY = 1, PX = 1, F = 14, OFF = 49152, NT = 4, WR = 2, WC = 2;
    __host__ __device__ static constexpr int DR(int a) { return a >> 1; }
    __host__ __device__ static constexpr int DC(int a) { return a & 1; }
    __host__ __device__ static constexpr int FS(int a) {
        int s = 0; for (int i = 0; i < a; i++) s += NT - i + 1; return s;
    }
};

#define CH 4

// --------------------------- staging (128 threads per half) ------------------
// Kernel frags (CH*F*64 floats) via cp.async; taps via coalesced float4 LDG
// -> 4x STS, PLAIN f32 layout sXu[cl][3 rows][34 cols].

template <int C>
__device__ __forceinline__ void stage(const float* __restrict__ x, float* sK,
                                      float* sXu, const float* gK, int cc0,
                                      int b, int ipair, int th) {
    using Cf = Cfg<C>;
    const float4* src = (const float4*)(gK + cc0 * Cf::F * 64);
    float4* dst = (float4*)sK;
#pragma unroll
    for (int idx = th; idx < Cf::F * 64; idx += 128)
        cp16(dst + idx, src + idx);
    if (th < 99) {
        int rr = th / 33, cc = th % 33;
        int r = ipair * 2 + rr;
        float4 v = make_float4(0.f, 0.f, 0.f, 0.f);
        if (r < 32 && cc < 32)
            v = *(const float4*)(x + (((b * 32 + r) * 32 + cc) << 6) + cc0);
        sXu[(0 * 3 + rr) * 34 + cc] = v.x;
        sXu[(1 * 3 + rr) * 34 + cc] = v.y;
        sXu[(2 * 3 + rr) * 34 + cc] = v.z;
        sXu[(3 * 3 + rr) * 34 + cc] = v.w;
    }
}

// --------------------------- compute ----------------------------------------
// Per cl: all F frags (2 couts each = one u64) live in registers; 16-pixel
// sweep with sliding tap window. Horner:
//   contribution = sum_a t_a * ( K_lin_a + sum_{b>=a} t_b * K_ab ).

template <int C>
__device__ __forceinline__ void compute_chunk(const float* sK, const float* sXu,
                                              int ii, int j0, int tx,
                                              u64 acc[16]) {
    using Cf = Cfg<C>;
#pragma unroll
    for (int cl = 0; cl < CH; cl++) {
        const float* kb = sK + cl * Cf::F * 64 + 2 * tx;
        u64 frg[Cf::F];
#pragma unroll
        for (int f = 0; f < Cf::F; f++)
            frg[f] = *(const u64*)(kb + f * 64);

        const float* tb = sXu + (cl * 3 + ii) * 34 + j0;

        u64 win[Cf::WR][Cf::WC];
#pragma unroll
        for (int r = 0; r < Cf::WR; r++)
#pragma unroll
            for (int c = 0; c < Cf::WC; c++)
                win[r][c] = pack2f(tb[r * 34 + c]);

#pragma unroll
        for (int p = 0; p < 16; p++) {
#pragma unroll
            for (int a = 0; a < Cf::NT; a++) {
                const int fs = Cf::FS(a);
                const int nb = Cf::NT - a;
                u64 t0 = frg[fs + nb];
#pragma unroll
                for (int b = Cf::NT - 1; b >= a; b--)
                    fma2(t0, win[Cf::DR(b)][Cf::DC(b)], frg[fs + b - a]);
                fma2(acc[p], win[Cf::DR(a)][Cf::DC(a)], t0);
            }
            if (p < 15) {
#pragma unroll
                for (int r = 0; r < Cf::WR; r++) {
#pragma unroll
                    for (int c = 0; c < Cf::WC - 1; c++) win[r][c] = win[r][c + 1];
                    win[r][Cf::WC - 1] = pack2f(tb[r * 34 + p + Cf::WC]);
                }
            }
        }
    }
}

// --------------------------- main kernel ------------------------------------
// CTA: 256 threads = two 128-thread cin-halves (h = t>>7). Per half:
// tx = th&31 -> couts 2tx,2tx+1 ; tyy = th>>5 -> 16 pixels at m0 = 16*tyy.
// 8 chunks of 4 cins, double-buffered, ONE named barrier per chunk:
//   wait_group 0 ; bar ; stage(next) ; commit ; compute(cur)

template <int C>
__device__ __forceinline__ void run_tile(const float* __restrict__ x,
                                         float* __restrict__ out, int tile) {
    using Cf = Cfg<C>;
    constexpr int KSZ = CH * Cf::F * 64;      // kernel chunk floats
    constexpr int TSZ = CH * 3 * 34;          // plain tap floats
    constexpr int BUF = KSZ + TSZ;

    extern __shared__ float sm[];

    const int t = threadIdx.x;
    const int h = t >> 7;
    const int th = t & 127;
    float* base = sm + h * 2 * BUF;

    const int b = tile >> 4;
    const int ipair = tile & 15;
    const int tx = th & 31;
    const int tyy = th >> 5;                // 0..3
    const int m0 = 16 * tyy;                // first of 16 pixels
    const int ii = m0 >> 5;                 // input row within pair
    const int j0 = m0 & 31;                 // 0 or 16

    u64 acc[16];
#pragma unroll
    for (int p = 0; p < 16; p++) acc[p] = 0ull;

    const float* gK = g_Kc + Cf::OFF;
    const int cbase = h * 32;

    stage<C>(x, base, base + KSZ, gK, cbase, b, ipair, th);
    CP_COMMIT();

    for (int ch = 0; ch < 8; ch++) {
        float* cbuf = base + (ch & 1) * BUF;
        float* nbuf = base + ((ch & 1) ^ 1) * BUF;
        cp_wait0();
        asm volatile("bar.sync %0, 128;" :: "r"(1 + h));
        if (ch < 7) {
            stage<C>(x, nbuf, nbuf + KSZ, gK, cbase + (ch + 1) * CH, b, ipair, th);
            CP_COMMIT();
        }
        compute_chunk<C>(cbuf, cbuf + KSZ, ii, j0, tx, acc);
    }

    // ---- reduction epilogue ----
    const int i = ipair * 2 + ii;
    const int ho = 2 * i + Cf::PY;

    if (h == 1) {   // store partials (cin 32..63)
#pragma unroll
        for (int p = 0; p < 16; p++) {
            const int wo = 2 * (j0 + p) + Cf::PX;
            float v0, v1;
            unpack2(acc[p], v0, v1);
            float* op = out + (((b * 64 + ho) * 64 + wo) << 6) + 2 * tx;
            *(float2*)op = make_float2(v0, v1);
        }
    }
    __syncthreads();
    if (h == 0) {   // add partial + bias, final store
        float2 bo = *(const float2*)(g_bias + 2 * tx);
#pragma unroll
        for (int p = 0; p < 16; p++) {
            const int wo = 2 * (j0 + p) + Cf::PX;
            float* op = out + (((b * 64 + ho) * 64 + wo) << 6) + 2 * tx;
            float2 o0 = *(const float2*)op;
            float v0, v1;
            unpack2(acc[p], v0, v1);
            *(float2*)op = make_float2(v0 + bo.x + o0.x, v1 + bo.y + o0.y);
        }
    }
}

__global__ __launch_bounds__(256, 2) void qct_main(const float* __restrict__ x,
                                                   float* __restrict__ out) {
    int id = blockIdx.x;
    // heavy class 3 first for wave balance
    if (id < 128)      run_tile<3>(x, out, id);
    else if (id < 256) run_tile<1>(x, out, id - 128);
    else if (id < 384) run_tile<2>(x, out, id - 256);
    else               run_tile<0>(x, out, id - 384);
}

// --------------------------- launch ----------------------------------------

extern "C" void kernel_launch(void* const* d_in, const int* in_sizes, int n_in,
                              void* d_out, int out_size) {
    const float* x  = (const float*)d_in[0];
    const float* fk = (const float*)d_in[1];
    if (n_in >= 2 && in_sizes[0] == 55 * 64 * 64) {  // defensive order check
        const float* tmp = x; x = fk; fk = tmp;
    }
    float* out = (float*)d_out;

    qct_prep<<<(4 * 14 * 4096 + 255) / 256, 256>>>(fk);

    // 2 halves x 2 buffers of (kernel chunk + plain taps), sized for class 3
    const int smem_bytes = 4 * (CH * 14 * 64 + CH * 3 * 34) * 4;  // 63872
    cudaFuncSetAttribute(qct_main, cudaFuncAttributeMaxDynamicSharedMemorySize,
                         smem_bytes);
    qct_main<<<512, 256, smem_bytes>>>(x, out);
}

// round 14
// speedup vs baseline: 1.2621x; 1.0058x over previous
#include <cuda_runtime.h>

// ---------------------------------------------------------------------------
// QuadraticConv2DTranspose via bed-of-nails sparsity.
//   B=8,H=W=32,CIN=COUT=64,k=3,s=2 -> out [8,64,64,64]
// Parity classes (ho%2,wo%2): NT {1,2,2,4} taps -> F {2,5,5,14} features.
// R14: kill the sliding tap window (serialized MOV+LDS chains were the
//      measured stall): per (cl, 8-px block) preload all tap columns into
//      directly-indexed registers in one LDS+pack batch, then run a pure
//      fma2 stretch (class3: 112 fma2) with short register-only chains.
//      Otherwise R13: 256 thr (256,2), 16px x 2co, CH=4, cp.async frags,
//      one barrier per chunk, cin-half split, gmem partial reduction.
// ---------------------------------------------------------------------------

typedef unsigned long long u64;

__device__ float g_Kc[106496];
__device__ float g_bias[64];

// Horner-ordered feature lists: per tap a: quads (a,b) b=a..NT-1, then lin_a.
__constant__ int c_L[4][14] = {
    {30,49, 0,0,0,0,0,0,0,0,0,0,0,0},
    {24,26,48,35,50, 0,0,0,0,0,0,0,0,0},
    { 9,15,46,42,52, 0,0,0,0,0,0,0,0,0},
    { 0, 2, 6, 8,45,17,21,23,47,39,41,51,44,53}
};
__constant__ int c_off[4] = {0, 8192, 28672, 49152};
__constant__ int c_Fn[4] = {2, 5, 5, 14};

// --------------------------- preprocessing ---------------------------------

__global__ void qct_prep(const float* __restrict__ fk) {
    int idx = blockIdx.x * 256 + threadIdx.x;
    if (blockIdx.x == 0 && threadIdx.x < 64) {
        int o = threadIdx.x;
        float s = 0.f;
#pragma unroll 8
        for (int c = 0; c < 64; c++) s += fk[(54 * 64 + c) * 64 + o];
        g_bias[o] = s;
    }
    if (idx >= 4 * 14 * 4096) return;
    int C = idx / (14 * 4096);
    int r = idx % (14 * 4096);
    int f = r / 4096;
    int co = r % 4096;
    int c = co >> 6, o = co & 63;
    if (f >= c_Fn[C]) return;
    g_Kc[c_off[C] + (c * c_Fn[C] + f) * 64 + o] = fk[(c_L[C][f] * 64 + c) * 64 + o];
}

// --------------------------- helpers ---------------------------------------

__device__ __forceinline__ void fma2(u64& d, u64 a, u64 b) {
    asm("fma.rn.f32x2 %0, %1, %2, %0;" : "+l"(d) : "l"(a), "l"(b));
}
__device__ __forceinline__ u64 pack2f(float v) {
    u64 r;
    unsigned int u = __float_as_uint(v);
    asm("mov.b64 %0, {%1, %1};" : "=l"(r) : "r"(u));
    return r;
}
__device__ __forceinline__ void unpack2(u64 v, float& lo, float& hi) {
    unsigned int a, b;
    asm("mov.b64 {%0, %1}, %2;" : "=r"(a), "=r"(b) : "l"(v));
    lo = __uint_as_float(a);
    hi = __uint_as_float(b);
}
__device__ __forceinline__ void cp16(void* dst_smem, const void* src) {
    unsigned sdst = (unsigned)__cvta_generic_to_shared(dst_smem);
    asm volatile("cp.async.cg.shared.global [%0], [%1], 16;" :: "r"(sdst), "l"(src));
}
#define CP_COMMIT() asm volatile("cp.async.commit_group;")
__device__ __forceinline__ void cp_wait0() {
    asm volatile("cp.async.wait_group 0;");
}

// --------------------------- class configs ---------------------------------
// Tap a at patch offset (DR(a), DC(a)); window spans WR rows x WC cols.
// Horner layout: FS(a)=group start; quad (a,b) at FS(a)+(b-a); lin at
// FS(a)+(NT-a).

template <int C> struct Cfg;
template <> struct Cfg<0> {   // (even, even): tap j=4
    static constexpr int PY = 0, PX = 0, F = 2, OFF = 0, NT = 1, WR = 1, WC = 1;
    __host__ __device__ static constexpr int DR(int) { return 0; }
    __host__ __device__ static constexpr int DC(int) { return 0; }
    __host__ __device__ static constexpr int FS(int a) {
        int s = 0; for (int i = 0; i < a; i++) s += NT - i + 1; return s;
    }
};
template <> struct Cfg<1> {   // (even, odd): taps j=3,5
    static constexpr int PY = 0, PX = 1, F = 5, OFF = 8192, NT = 2, WR = 1, WC = 2;
    __host__ __device__ static constexpr int DR(int) { return 0; }
    __host__ __device__ static constexpr int DC(int a) { return a; }
    __host__ __device__ static constexpr int FS(int a) {
        int s = 0; for (int i = 0; i < a; i++) s += NT - i + 1; return s;
    }
};
template <> struct Cfg<2> {   // (odd, even): taps j=1,7
    static constexpr int PY = 1, PX = 0, F = 5, OFF = 28672, NT = 2, WR = 2, WC = 1;
    __host__ __device__ static constexpr int DR(int a) { return a; }
    __host__ __device__ static constexpr int DC(int) { return 0; }
    __host__ __device__ static constexpr int FS(int a) {
        int s = 0; for (int i = 0; i < a; i++) s += NT - i + 1; return s;
    }
};
template <> struct Cfg<3> {   // (odd, odd): taps j=0,2,6,8
    static constexpr int PY = 1, PX = 1, F = 14, OFF = 49152, NT = 4, WR = 2, WC = 2;
    __host__ __device__ static constexpr int DR(int a) { return a >> 1; }
    __host__ __device__ static constexpr int DC(int a) { return a & 1; }
    __host__ __device__ static constexpr int FS(int a) {
        int s = 0; for (int i = 0; i < a; i++) s += NT - i + 1; return s;
    }
};

#define CH 4

// --------------------------- staging (128 threads per half) ------------------
// Kernel frags (CH*F*64 floats) via cp.async; taps via coalesced float4 LDG
// -> 4x STS, PLAIN f32 layout sXu[cl][3 rows][34 cols].

template <int C>
__device__ __forceinline__ void stage(const float* __restrict__ x, float* sK,
                                      float* sXu, const float* gK, int cc0,
                                      int b, int ipair, int th) {
    using Cf = Cfg<C>;
    const float4* src = (const float4*)(gK + cc0 * Cf::F * 64);
    float4* dst = (float4*)sK;
#pragma unroll
    for (int idx = th; idx < Cf::F * 64; idx += 128)
        cp16(dst + idx, src + idx);
    if (th < 99) {
        int rr = th / 33, cc = th % 33;
        int r = ipair * 2 + rr;
        float4 v = make_float4(0.f, 0.f, 0.f, 0.f);
        if (r < 32 && cc < 32)
            v = *(const float4*)(x + (((b * 32 + r) * 32 + cc) << 6) + cc0);
        sXu[(0 * 3 + rr) * 34 + cc] = v.x;
        sXu[(1 * 3 + rr) * 34 + cc] = v.y;
        sXu[(2 * 3 + rr) * 34 + cc] = v.z;
        sXu[(3 * 3 + rr) * 34 + cc] = v.w;
    }
}

// --------------------------- compute ----------------------------------------
// Per (cl, 8-px block): preload taps into directly-indexed regs (one LDS+pack
// batch), then a pure-fma2 stretch. Horner:
//   contribution = sum_a t_a * ( K_lin_a + sum_{b>=a} t_b * K_ab ).

template <int C>
__device__ __forceinline__ void compute_chunk(const float* sK, const float* sXu,
                                              int ii, int j0, int tx,
                                              u64 acc[16]) {
    using Cf = Cfg<C>;
    constexpr int NCOL = 8 + Cf::WC - 1;    // tap cols per 8-px block
#pragma unroll
    for (int cl = 0; cl < CH; cl++) {
        const float* kb = sK + cl * Cf::F * 64 + 2 * tx;
        u64 frg[Cf::F];
#pragma unroll
        for (int f = 0; f < Cf::F; f++)
            frg[f] = *(const u64*)(kb + f * 64);

        const float* tb = sXu + (cl * 3 + ii) * 34 + j0;

#pragma unroll
        for (int blk = 0; blk < 2; blk++) {
            const float* tc = tb + 8 * blk;
            u64 win[Cf::WR][NCOL];
#pragma unroll
            for (int r = 0; r < Cf::WR; r++)
#pragma unroll
                for (int c = 0; c < NCOL; c++)
                    win[r][c] = pack2f(tc[r * 34 + c]);

#pragma unroll
            for (int p = 0; p < 8; p++) {
#pragma unroll
                for (int a = 0; a < Cf::NT; a++) {
                    const int fs = Cf::FS(a);
                    const int nb = Cf::NT - a;
                    u64 t0 = frg[fs + nb];
#pragma unroll
                    for (int b = Cf::NT - 1; b >= a; b--)
                        fma2(t0, win[Cf::DR(b)][p + Cf::DC(b)], frg[fs + b - a]);
                    fma2(acc[8 * blk + p], win[Cf::DR(a)][p + Cf::DC(a)], t0);
                }
            }
        }
    }
}

// --------------------------- main kernel ------------------------------------
// CTA: 256 threads = two 128-thread cin-halves (h = t>>7). Per half:
// tx = th&31 -> couts 2tx,2tx+1 ; tyy = th>>5 -> 16 pixels at m0 = 16*tyy.
// 8 chunks of 4 cins, double-buffered, ONE named barrier per chunk:
//   wait_group 0 ; bar ; stage(next) ; commit ; compute(cur)

template <int C>
__device__ __forceinline__ void run_tile(const float* __restrict__ x,
                                         float* __restrict__ out, int tile) {
    using Cf = Cfg<C>;
    constexpr int KSZ = CH * Cf::F * 64;      // kernel chunk floats
    constexpr int TSZ = CH * 3 * 34;          // plain tap floats
    constexpr int BUF = KSZ + TSZ;

    extern __shared__ float sm[];

    const int t = threadIdx.x;
    const int h = t >> 7;
    const int th = t & 127;
    float* base = sm + h * 2 * BUF;

    const int b = tile >> 4;
    const int ipair = tile & 15;
    const int tx = th & 31;
    const int tyy = th >> 5;                // 0..3
    const int m0 = 16 * tyy;                // first of 16 pixels
    const int ii = m0 >> 5;                 // input row within pair
    const int j0 = m0 & 31;                 // 0 or 16

    u64 acc[16];
#pragma unroll
    for (int p = 0; p < 16; p++) acc[p] = 0ull;

    const float* gK = g_Kc + Cf::OFF;
    const int cbase = h * 32;

    stage<C>(x, base, base + KSZ, gK, cbase, b, ipair, th);
    CP_COMMIT();

    for (int ch = 0; ch < 8; ch++) {
        float* cbuf = base + (ch & 1) * BUF;
        float* nbuf = base + ((ch & 1) ^ 1) * BUF;
        cp_wait0();
        asm volatile("bar.sync %0, 128;" :: "r"(1 + h));
        if (ch < 7) {
            stage<C>(x, nbuf, nbuf + KSZ, gK, cbase + (ch + 1) * CH, b, ipair, th);
            CP_COMMIT();
        }
        compute_chunk<C>(cbuf, cbuf + KSZ, ii, j0, tx, acc);
    }

    // ---- reduction epilogue ----
    const int i = ipair * 2 + ii;
    const int ho = 2 * i + Cf::PY;

    if (h == 1) {   // store partials (cin 32..63)
#pragma unroll
        for (int p = 0; p < 16; p++) {
            const int wo = 2 * (j0 + p) + Cf::PX;
            float v0, v1;
            unpack2(acc[p], v0, v1);
            float* op = out + (((b * 64 + ho) * 64 + wo) << 6) + 2 * tx;
            *(float2*)op = make_float2(v0, v1);
        }
    }
    __syncthreads();
    if (h == 0) {   // add partial + bias, final store
        float2 bo = *(const float2*)(g_bias + 2 * tx);
#pragma unroll
        for (int p = 0; p < 16; p++) {
            const int wo = 2 * (j0 + p) + Cf::PX;
            float* op = out + (((b * 64 + ho) * 64 + wo) << 6) + 2 * tx;
            float2 o0 = *(const float2*)op;
            float v0, v1;
            unpack2(acc[p], v0, v1);
            *(float2*)op = make_float2(v0 + bo.x + o0.x, v1 + bo.y + o0.y);
        }
    }
}

__global__ __launch_bounds__(256, 2) void qct_main(const float* __restrict__ x,
                                                   float* __restrict__ out) {
    int id = blockIdx.x;
    // heavy class 3 first for wave balance
    if (id < 128)      run_tile<3>(x, out, id);
    else if (id < 256) run_tile<1>(x, out, id - 128);
    else if (id < 384) run_tile<2>(x, out, id - 256);
    else               run_tile<0>(x, out, id - 384);
}

// --------------------------- launch ----------------------------------------

extern "C" void kernel_launch(void* const* d_in, const int* in_sizes, int n_in,
                              void* d_out, int out_size) {
    const float* x  = (const float*)d_in[0];
    const float* fk = (const float*)d_in[1];
    if (n_in >= 2 && in_sizes[0] == 55 * 64 * 64) {  // defensive order check
        const float* tmp = x; x = fk; fk = tmp;
    }
    float* out = (float*)d_out;

    qct_prep<<<(4 * 14 * 4096 + 255) / 256, 256>>>(fk);

    // 2 halves x 2 buffers of (kernel chunk + plain taps), sized for class 3
    const int smem_bytes = 4 * (CH * 14 * 64 + CH * 3 * 34) * 4;  // 63872
    cudaFuncSetAttribute(qct_main, cudaFuncAttributeMaxDynamicSharedMemorySize,
                         smem_bytes);
    qct_main<<<512, 256, smem_bytes>>>(x, out);
}